// round 8
// baseline (speedup 1.0000x reference)
#include <cuda_runtime.h>
#include <cstdint>

// Problem constants (fixed by the reference)
#define BATCH      512
#define SEQ        200
#define HALF       100   // t-range per te_main block
#define EMB        256
#define NUM_SKILLS 300
#define D3         21    // CURVE_DIM//3
#define CHUNK      10    // rows per TMA store chunk (10 KB)
#define NCHUNK     (HALF / CHUNK)

// Precomputed affine basis: traj[b,t,e] = qf*A[e] + att*B[e] + mast*C[e] + D[e]
__device__ __align__(16) float g_A[EMB];
__device__ __align__(16) float g_B[EMB];
__device__ __align__(16) float g_C[EMB];
__device__ __align__(16) float g_D[EMB];

__device__ __forceinline__ uint32_t smem_u32(const void* p) {
    return (uint32_t)__cvta_generic_to_shared(p);
}

// ---------------------------------------------------------------------------
// Precompute: warp-per-embedding-row, fully coalesced. 8 blocks x 256 threads.
// ---------------------------------------------------------------------------
__global__ __launch_bounds__(256) void te_precompute(const float* __restrict__ skill_w,
                                                     const float* __restrict__ skill_b,
                                                     const float* __restrict__ att_w,
                                                     const float* __restrict__ att_b,
                                                     const float* __restrict__ mast_w,
                                                     const float* __restrict__ mast_b,
                                                     const float* __restrict__ proj_w,
                                                     const float* __restrict__ proj_b) {
    const int lane = threadIdx.x & 31;
    const int wid  = (blockIdx.x * blockDim.x + threadIdx.x) >> 5;  // global warp 0..63

    const int   c1  = lane + 32;
    const float w0  = (lane < D3) ? skill_w[lane] : att_w[lane - D3];
    const float bw0 = (lane < D3) ? skill_b[lane] : att_b[lane - D3];
    const float w1  = (c1 < 2 * D3) ? att_w[c1 - D3] : mast_w[c1 - 2 * D3];
    const float bw1 = (c1 < 2 * D3) ? att_b[c1 - D3] : mast_b[c1 - 2 * D3];
    const bool  seg0_is_a = (lane < D3);
    const bool  seg1_is_b = (c1 < 2 * D3);

#pragma unroll
    for (int j = 0; j < 4; j++) {
        const int e = wid * 4 + j;
        const float x0 = proj_w[e * 64 + lane];   // coalesced
        const float x1 = proj_w[e * 64 + c1];     // coalesced

        const float t0 = w0 * x0;
        const float t1 = w1 * x1;
        float pa = seg0_is_a ? t0 : 0.f;
        float pb = (seg0_is_a ? 0.f : t0) + (seg1_is_b ? t1 : 0.f);
        float pc = seg1_is_b ? 0.f : t1;
        float pd = fmaf(bw0, x0, bw1 * x1);

#pragma unroll
        for (int off = 16; off >= 1; off >>= 1) {
            pa += __shfl_xor_sync(0xffffffffu, pa, off);
            pb += __shfl_xor_sync(0xffffffffu, pb, off);
            pc += __shfl_xor_sync(0xffffffffu, pc, off);
            pd += __shfl_xor_sync(0xffffffffu, pd, off);
        }
        if (lane == 0) {
            g_A[e] = pa;
            g_B[e] = pb;
            g_C[e] = pc;
            g_D[e] = pd + proj_b[e];
        }
    }
}

// ---------------------------------------------------------------------------
// Main: 1024 blocks (2 per batch row) x 256 threads, 8 blocks/SM (one wave).
// Phase 1: running counts by direct counting (parallel over t).
// Phase 2: compute rows into double-buffered smem staging; hand 10KB chunks to
//          the async bulk-copy engine (cp.async.bulk S->G). STS is issue-only,
//          so warp streams carry no tracked global-store latency.
// ---------------------------------------------------------------------------
__global__ __launch_bounds__(256, 8) void te_main(const int* __restrict__ q,
                                                  const int* __restrict__ r,
                                                  float* __restrict__ out) {
    __shared__ __align__(16) float sbuf[2][CHUNK * EMB];   // 2 x 10KB staging
    __shared__ int    sq[SEQ];
    __shared__ int    sr[SEQ];
    __shared__ __align__(16) float4 s_scal[HALF];          // {qf, att, mast, valid}

    const int b   = blockIdx.x >> 1;
    const int t0  = (blockIdx.x & 1) * HALF;
    const int tid = threadIdx.x;

    if (tid < SEQ) {
        sq[tid] = q[b * SEQ + tid];
        sr[tid] = r[b * SEQ + tid];
    }
    __syncthreads();

    // Phase 1: attempts[t] = #{t' <= t : valid(t') && q[t']==q[t]}, correct w/ r.
    if (tid < HALF) {
        const int t  = t0 + tid;
        const int qt = sq[t];
        int att = 0, cor = 0;
        for (int tp = 0; tp <= t; tp++) {
            int qp = sq[tp];                    // warp-broadcast smem read
            if ((unsigned)qp < NUM_SKILLS && qp == qt) {
                att += 1;
                cor += sr[tp];
            }
        }
        const float v  = ((unsigned)qt < NUM_SKILLS) ? 1.0f : 0.0f;
        const float af = (float)att;
        s_scal[tid] = make_float4(v * (float)qt,
                                  v * af,
                                  v * ((float)cor / fmaxf(af, 1.0f)),
                                  v);
    }
    __syncthreads();

    // Phase 2
    const int lane = tid & 63;   // float4 index within the 256-wide row
    const int tg   = tid >> 6;   // 0..3

    const float4 A  = reinterpret_cast<const float4*>(g_A)[lane];
    const float4 Bv = reinterpret_cast<const float4*>(g_B)[lane];
    const float4 C  = reinterpret_cast<const float4*>(g_C)[lane];
    const float4 D  = reinterpret_cast<const float4*>(g_D)[lane];

    char* gdst = reinterpret_cast<char*>(out) + (size_t)(b * SEQ + t0) * EMB * 4;

#pragma unroll
    for (int c = 0; c < NCHUNK; ++c) {
        const int buf = c & 1;
        // Buffer reuse: the bulk copy issued at iteration c-2 must have finished
        // READING this buffer. wait_group.read allows its global write to still
        // be in flight (only the smem read side must drain).
        if (c >= 2 && tid == 0) {
            asm volatile("cp.async.bulk.wait_group.read 1;" ::: "memory");
        }
        __syncthreads();

        float4* __restrict__ dst4 = reinterpret_cast<float4*>(sbuf[buf]);
#pragma unroll
        for (int i = tg; i < CHUNK; i += 4) {
            const float4 s = s_scal[c * CHUNK + i];   // one LDS.128, broadcast
            float4 o;
            o.x = fmaf(s.x, A.x, fmaf(s.y, Bv.x, fmaf(s.z, C.x, s.w * D.x)));
            o.y = fmaf(s.x, A.y, fmaf(s.y, Bv.y, fmaf(s.z, C.y, s.w * D.y)));
            o.z = fmaf(s.x, A.z, fmaf(s.y, Bv.z, fmaf(s.z, C.z, s.w * D.z)));
            o.w = fmaf(s.x, A.w, fmaf(s.y, Bv.w, fmaf(s.z, C.w, s.w * D.w)));
            dst4[i * (EMB / 4) + lane] = o;           // STS.128, conflict-free
        }
        __syncthreads();

        if (tid == 0) {
            // Order generic-proxy STS before async-proxy bulk read.
            asm volatile("fence.proxy.async.shared::cta;" ::: "memory");
            asm volatile(
                "cp.async.bulk.global.shared::cta.bulk_group [%0], [%1], %2;"
                :: "l"(gdst + (size_t)c * CHUNK * EMB * 4),
                   "r"(smem_u32(&sbuf[buf][0])),
                   "r"((uint32_t)(CHUNK * EMB * 4))
                : "memory");
            asm volatile("cp.async.bulk.commit_group;" ::: "memory");
        }
    }

    // All bulk stores must retire before the CTA exits.
    if (tid == 0) {
        asm volatile("cp.async.bulk.wait_group 0;" ::: "memory");
    }
}

extern "C" void kernel_launch(void* const* d_in, const int* in_sizes, int n_in,
                              void* d_out, int out_size) {
    // metadata order: q, r, qry, skill_w, skill_b, att_w, att_b,
    //                 mast_w, mast_b, proj_w, proj_b
    const int*   q       = (const int*)d_in[0];
    const int*   r       = (const int*)d_in[1];
    // d_in[2] = qry — unused by the reference
    const float* skill_w = (const float*)d_in[3];
    const float* skill_b = (const float*)d_in[4];
    const float* att_w   = (const float*)d_in[5];
    const float* att_b   = (const float*)d_in[6];
    const float* mast_w  = (const float*)d_in[7];
    const float* mast_b  = (const float*)d_in[8];
    const float* proj_w  = (const float*)d_in[9];
    const float* proj_b  = (const float*)d_in[10];
    float* out = (float*)d_out;

    te_precompute<<<8, 256>>>(skill_w, skill_b, att_w, att_b,
                              mast_w, mast_b, proj_w, proj_b);
    te_main<<<BATCH * 2, 256>>>(q, r, out);
}